// round 13
// baseline (speedup 1.0000x reference)
#include <cuda_runtime.h>
#include <cuda_fp16.h>
#include <cstdint>

#define T_TOK 2048
#define DDIM  2048
#define NOUT  11264
#define LEXP  16
#define HALF_B 5632

// ---------------- scratch (device globals: allocation-free) ----------------
__device__ __align__(16) __half g_xh[(size_t)T_TOK * DDIM];  // fp16-rounded x
__device__ __align__(16) __half g_wh[(size_t)NOUT * DDIM];   // fp16-rounded W
__device__ float g_xa[T_TOK * 32];                           // xa = x . A[l]
__device__ int   g_tok[T_TOK];                               // tokens sorted by expert
__device__ int   g_start[LEXP + 1];                          // expert segment starts

// ---------------- kernel 1: bucket tokens by expert + zero xa ----------------
__global__ __launch_bounds__(1024) void sort_kernel(const void* idx_raw) {
    __shared__ int cnt[LEXP];
    __shared__ int base[LEXP];
    __shared__ int is64;
    int tid = threadIdx.x;
    if (tid < LEXP) cnt[tid] = 0;
    if (tid == 0) is64 = 1;
    __syncthreads();

    // sniff int32 vs int64: if int64 (values in [0,16)), every odd 32-bit word is 0
    const int* a32 = (const int*)idx_raw;
    for (int j = tid; j < 1024; j += blockDim.x)
        if (a32[2 * j + 1] != 0) is64 = 0;   // benign race
    __syncthreads();
    const long long* a64 = (const long long*)idx_raw;
    int use64 = is64;

    for (int t = tid; t < T_TOK; t += blockDim.x) {
        int l = use64 ? (int)a64[t] : a32[t];
        atomicAdd(&cnt[l], 1);
    }
    __syncthreads();
    if (tid == 0) {
        int s = 0;
        for (int l = 0; l < LEXP; ++l) { base[l] = s; g_start[l] = s; s += cnt[l]; }
        g_start[LEXP] = s;
    }
    __syncthreads();
    for (int t = tid; t < T_TOK; t += blockDim.x) {
        int l = use64 ? (int)a64[t] : a32[t];
        int p = atomicAdd(&base[l], 1);
        g_tok[p] = t;
    }
    for (int i = tid; i < T_TOK * 32; i += blockDim.x) g_xa[i] = 0.0f;
}

// ---------------- kernel 2: round x and W to fp16 (RN) ----------------
__global__ __launch_bounds__(256) void round_kernel(const float4* __restrict__ x,
                                                    const float4* __restrict__ W) {
    const size_t nx = (size_t)T_TOK * DDIM / 4;
    const size_t nw = (size_t)NOUT * DDIM / 4;
    __half2* ox = (__half2*)g_xh;
    __half2* ow = (__half2*)g_wh;
    size_t stride = (size_t)gridDim.x * blockDim.x;
    for (size_t i = (size_t)blockIdx.x * blockDim.x + threadIdx.x; i < nx + nw; i += stride) {
        float4 v;
        __half2* dst;
        if (i < nx) { v = x[i]; dst = ox + 2 * i; }
        else        { v = W[i - nx]; dst = ow + 2 * (i - nx); }
        dst[0] = __floats2half2_rn(v.x, v.y);
        dst[1] = __floats2half2_rn(v.z, v.w);
    }
}

// ---------------- kernel 3: xa[t, j] = sum_d x[t,d] * A[l, d, j] ----------------
__global__ __launch_bounds__(512) void xa_kernel(const float* __restrict__ x,
                                                 const float* __restrict__ A) {
    __shared__ float As[128 * 32];
    int l = blockIdx.y;
    int d0 = blockIdx.x * 128;
    int tid = threadIdx.x;
    int lane = tid & 31, w = tid >> 5;

    size_t abase = ((size_t)l * DDIM + d0) * 32;
    for (int i = tid; i < 128 * 32; i += 512) As[i] = A[abase + i];
    __syncthreads();

    int pbeg = g_start[l], pend = g_start[l + 1];
    for (int p = pbeg + w; p < pend; p += 16) {
        int t = g_tok[p];
        float xv[4];
#pragma unroll
        for (int s = 0; s < 4; ++s)
            xv[s] = x[(size_t)t * DDIM + d0 + s * 32 + lane];
        float acc = 0.0f;
#pragma unroll
        for (int s = 0; s < 4; ++s) {
#pragma unroll
            for (int i = 0; i < 32; ++i) {
                float xb = __shfl_sync(0xffffffffu, xv[s], i);
                acc += xb * As[(s * 32 + i) * 32 + lane];
            }
        }
        atomicAdd(&g_xa[t * 32 + lane], acc);
    }
}

// ---------------- kernel 4: delta -> out (full init), B in regs, 4-way z-split
__global__ __launch_bounds__(256) void delta_kernel(const float* __restrict__ B,
                                                    float* __restrict__ out) {
    int l = blockIdx.y;
    int n0 = blockIdx.x * 512;
    int half = (n0 >= HALF_B) ? 1 : 0;
    int tid = threadIdx.x;
    int c0 = n0 + 2 * tid;

    int pbeg = g_start[l], pend = g_start[l + 1];
    int len = pend - pbeg;
    int per = (len + 3) >> 2;
    int s = pbeg + blockIdx.z * per;
    int e = s + per;
    if (e > pend) e = pend;
    if (s >= e) return;

    float2 Breg[16];
#pragma unroll
    for (int r = 0; r < 16; ++r)
        Breg[r] = *(const float2*)(B + ((size_t)l * 16 + r) * NOUT + c0);

    const float4* xa4base = (const float4*)(g_xa) + half * 4;

    for (int p = s; p < e; ++p) {
        int t = g_tok[p];
        float4 x0 = __ldg(xa4base + t * 8 + 0);
        float4 x1 = __ldg(xa4base + t * 8 + 1);
        float4 x2 = __ldg(xa4base + t * 8 + 2);
        float4 x3 = __ldg(xa4base + t * 8 + 3);
        float xs[16] = {x0.x, x0.y, x0.z, x0.w, x1.x, x1.y, x1.z, x1.w,
                        x2.x, x2.y, x2.z, x2.w, x3.x, x3.y, x3.z, x3.w};
        float2 acc = make_float2(0.0f, 0.0f);
#pragma unroll
        for (int r = 0; r < 16; ++r) {
            acc.x += xs[r] * Breg[r].x;
            acc.y += xs[r] * Breg[r].y;
        }
        *(float2*)(out + (size_t)t * NOUT + c0) = acc;
    }
}

// ------- kernel 5: main GEMM (fp16 mma.sync m16n8k16, BK=64, 3 stages) -------
#define BM 128
#define BN 128
#define BK 64
#define PADH 72                         // halfs per smem row: 144 B stride (16B-aligned, conflict-free)
#define STAGES 3
#define STAGE_BYTES ((BM + BN) * PADH * 2)   // 36864 B
#define SMEM_GEMM (STAGES * STAGE_BYTES)     // 110592 B -> 2 CTAs/SM (221 KB of 228 KB)

__device__ __forceinline__ void cpa16(uint32_t s, const void* g) {
    asm volatile("cp.async.cg.shared.global [%0], [%1], 16;\n" :: "r"(s), "l"(g));
}

__global__ __launch_bounds__(256, 2) void gemm_kernel(float* __restrict__ out) {
    extern __shared__ __half smem[];

    int tid = threadIdx.x;
    int lane = tid & 31;
    int warp = tid >> 5;
    int warpM = warp & 3;    // 4 warps in M  -> 32 rows each
    int warpN = warp >> 2;   // 2 warps in N  -> 64 cols each
    int grp = lane >> 2;     // 0..7
    int qid = lane & 3;      // 0..3

    int bm = blockIdx.x;     // 0..15
    int bn = blockIdx.y;     // 0..87

    const __half* gA = g_xh + (size_t)(bm * BM) * DDIM;
    const __half* gB = g_wh + (size_t)(bn * BN) * DDIM;

    // cp.async mapping: 256 rows x 8 segs of 16B (128 B per row); 8 chunks/thread
    int rbase = tid >> 3;    // 0..31
    int seg = tid & 7;       // 0..7

    uint32_t sBase = (uint32_t)__cvta_generic_to_shared(smem);

    float c[2][8][4];
#pragma unroll
    for (int mt = 0; mt < 2; ++mt)
#pragma unroll
        for (int nt = 0; nt < 8; ++nt)
#pragma unroll
            for (int i = 0; i < 4; ++i) c[mt][nt][i] = 0.0f;

    auto loadTiles = [&](int buf, int k0) {
        uint32_t soff = sBase + (uint32_t)buf * STAGE_BYTES;
#pragma unroll
        for (int i = 0; i < 8; ++i) {
            int row = rbase + i * 32;          // 0..255 (A rows 0-127, B rows 128-255)
            const __half* src = (row < BM)
                ? (gA + (size_t)row * DDIM + k0 + seg * 8)
                : (gB + (size_t)(row - BM) * DDIM + k0 + seg * 8);
            cpa16(soff + (uint32_t)(row * PADH * 2 + seg * 16), src);
        }
        asm volatile("cp.async.commit_group;\n");
    };

    auto compute = [&](uint32_t base) {   // base = sBase + buf*STAGE_BYTES
        uint32_t aRowOff = (uint32_t)((warpM * 32 + grp) * PADH * 2);
        uint32_t bRowOff = (uint32_t)(BM * PADH * 2 + (warpN * 64 + grp) * PADH * 2);
#pragma unroll
        for (int ks = 0; ks < 4; ++ks) {     // four k16 steps cover BK=64
            uint32_t kb = (uint32_t)(ks * 32 + qid * 4);   // byte offset in row
            uint32_t a[2][4], b[8][2];
#pragma unroll
            for (int mt = 0; mt < 2; ++mt) {
                uint32_t r0 = base + aRowOff + (uint32_t)(mt * 16 * PADH * 2) + kb;
                uint32_t r1 = r0 + (uint32_t)(8 * PADH * 2);
                asm volatile("ld.shared.b32 %0, [%1];" : "=r"(a[mt][0]) : "r"(r0));
                asm volatile("ld.shared.b32 %0, [%1];" : "=r"(a[mt][1]) : "r"(r1));
                asm volatile("ld.shared.b32 %0, [%1];" : "=r"(a[mt][2]) : "r"(r0 + 16));
                asm volatile("ld.shared.b32 %0, [%1];" : "=r"(a[mt][3]) : "r"(r1 + 16));
            }
#pragma unroll
            for (int nt = 0; nt < 8; ++nt) {
                uint32_t rb = base + bRowOff + (uint32_t)(nt * 8 * PADH * 2) + kb;
                asm volatile("ld.shared.b32 %0, [%1];" : "=r"(b[nt][0]) : "r"(rb));
                asm volatile("ld.shared.b32 %0, [%1];" : "=r"(b[nt][1]) : "r"(rb + 16));
            }
#pragma unroll
            for (int mt = 0; mt < 2; ++mt) {
#pragma unroll
                for (int nt = 0; nt < 8; ++nt) {
                    asm volatile(
                        "mma.sync.aligned.m16n8k16.row.col.f32.f16.f16.f32 "
                        "{%0,%1,%2,%3}, {%4,%5,%6,%7}, {%8,%9}, {%0,%1,%2,%3};\n"
                        : "+f"(c[mt][nt][0]), "+f"(c[mt][nt][1]),
                          "+f"(c[mt][nt][2]), "+f"(c[mt][nt][3])
                        : "r"(a[mt][0]), "r"(a[mt][1]), "r"(a[mt][2]), "r"(a[mt][3]),
                          "r"(b[nt][0]), "r"(b[nt][1]));
                }
            }
        }
    };

    loadTiles(0, 0);
    loadTiles(1, BK);

    const int NITER = DDIM / BK;   // 32
    // 3-stage pipeline, wait_group 1 steady state, unrolled x3 so stage bases
    // are compile-time constants. Awaited load has had 2 full rounds to land.
#pragma unroll 1
    for (int it = 0; it < NITER - 4; it += 3) {   // rounds 0..29
#pragma unroll
        for (int u = 0; u < 3; ++u) {
            asm volatile("cp.async.wait_group 1;\n");
            __syncthreads();
            loadTiles((u + 2) % STAGES, (it + u + 2) * BK);
            compute(sBase + (uint32_t)u * STAGE_BYTES);
        }
    }
    // tail: rounds 30, 31  (30 % 3 == 0)
#pragma unroll
    for (int u = 0; u < 2; ++u) {
        int it = 30 + u;
        if (it < NITER - 1) {
            asm volatile("cp.async.wait_group 1;\n");
        } else {
            asm volatile("cp.async.wait_group 0;\n");
        }
        __syncthreads();
        compute(sBase + (uint32_t)(u * STAGE_BYTES));
    }

    // epilogue: out += acc (out already holds delta)
#pragma unroll
    for (int mt = 0; mt < 2; ++mt) {
#pragma unroll
        for (int nt = 0; nt < 8; ++nt) {
            int r = bm * BM + warpM * 32 + mt * 16 + grp;
            int col = bn * BN + warpN * 64 + nt * 8 + qid * 2;
            size_t o = (size_t)r * NOUT + col;
            float2* p0 = (float2*)(out + o);
            float2 v0 = *p0;
            v0.x += c[mt][nt][0];
            v0.y += c[mt][nt][1];
            *p0 = v0;
            float2* p1 = (float2*)(out + o + (size_t)8 * NOUT);
            float2 v1 = *p1;
            v1.x += c[mt][nt][2];
            v1.y += c[mt][nt][3];
            *p1 = v1;
        }
    }
}

// ---------------- launch ----------------
extern "C" void kernel_launch(void* const* d_in, const int* in_sizes, int n_in,
                              void* d_out, int out_size) {
    const float* x = (const float*)d_in[0];
    const float* W = (const float*)d_in[1];
    const float* A = (const float*)d_in[2];
    const float* B = (const float*)d_in[3];
    const void*  idx = d_in[4];
    float* out = (float*)d_out;

    (void)in_sizes; (void)n_in; (void)out_size;

    cudaFuncSetAttribute(gemm_kernel, cudaFuncAttributeMaxDynamicSharedMemorySize, SMEM_GEMM);

    sort_kernel<<<1, 1024>>>(idx);
    round_kernel<<<2048, 256>>>((const float4*)x, (const float4*)W);
    xa_kernel<<<dim3(16, 16), 512>>>(x, A);
    delta_kernel<<<dim3(22, 16, 4), 256>>>(B, out);
    gemm_kernel<<<dim3(16, 88), 256, SMEM_GEMM>>>(out);
}

// round 14
// speedup vs baseline: 1.0253x; 1.0253x over previous
#include <cuda_runtime.h>
#include <cuda_fp16.h>
#include <cstdint>

#define T_TOK 2048
#define DDIM  2048
#define NOUT  11264
#define LEXP  16
#define HALF_B 5632

// ---------------- scratch (device globals: allocation-free) ----------------
__device__ __align__(16) __half g_xh[(size_t)T_TOK * DDIM];  // fp16-rounded x
__device__ __align__(16) __half g_wh[(size_t)NOUT * DDIM];   // fp16-rounded W
__device__ float g_xa[T_TOK * 32];                           // xa = x . A[l]
__device__ int   g_tok[T_TOK];                               // tokens sorted by expert
__device__ int   g_start[LEXP + 1];                          // expert segment starts

// ---------------- kernel 1: bucket tokens by expert + zero xa ----------------
__global__ __launch_bounds__(1024) void sort_kernel(const void* idx_raw) {
    __shared__ int cnt[LEXP];
    __shared__ int base[LEXP];
    __shared__ int is64;
    int tid = threadIdx.x;
    if (tid < LEXP) cnt[tid] = 0;
    if (tid == 0) is64 = 1;
    __syncthreads();

    // sniff int32 vs int64: if int64 (values in [0,16)), every odd 32-bit word is 0
    const int* a32 = (const int*)idx_raw;
    for (int j = tid; j < 1024; j += blockDim.x)
        if (a32[2 * j + 1] != 0) is64 = 0;   // benign race
    __syncthreads();
    const long long* a64 = (const long long*)idx_raw;
    int use64 = is64;

    for (int t = tid; t < T_TOK; t += blockDim.x) {
        int l = use64 ? (int)a64[t] : a32[t];
        atomicAdd(&cnt[l], 1);
    }
    __syncthreads();
    if (tid == 0) {
        int s = 0;
        for (int l = 0; l < LEXP; ++l) { base[l] = s; g_start[l] = s; s += cnt[l]; }
        g_start[LEXP] = s;
    }
    __syncthreads();
    for (int t = tid; t < T_TOK; t += blockDim.x) {
        int l = use64 ? (int)a64[t] : a32[t];
        int p = atomicAdd(&base[l], 1);
        g_tok[p] = t;
    }
    for (int i = tid; i < T_TOK * 32; i += blockDim.x) g_xa[i] = 0.0f;
}

// ---------------- kernel 2: round x and W to fp16 (RN) ----------------
__global__ __launch_bounds__(256) void round_kernel(const float4* __restrict__ x,
                                                    const float4* __restrict__ W) {
    const size_t nx = (size_t)T_TOK * DDIM / 4;
    const size_t nw = (size_t)NOUT * DDIM / 4;
    __half2* ox = (__half2*)g_xh;
    __half2* ow = (__half2*)g_wh;
    size_t stride = (size_t)gridDim.x * blockDim.x;
    for (size_t i = (size_t)blockIdx.x * blockDim.x + threadIdx.x; i < nx + nw; i += stride) {
        float4 v;
        __half2* dst;
        if (i < nx) { v = x[i]; dst = ox + 2 * i; }
        else        { v = W[i - nx]; dst = ow + 2 * (i - nx); }
        dst[0] = __floats2half2_rn(v.x, v.y);
        dst[1] = __floats2half2_rn(v.z, v.w);
    }
}

// ---------------- kernel 3: xa[t, j] = sum_d x[t,d] * A[l, d, j] ----------------
__global__ __launch_bounds__(512) void xa_kernel(const float* __restrict__ x,
                                                 const float* __restrict__ A) {
    __shared__ float As[128 * 32];
    int l = blockIdx.y;
    int d0 = blockIdx.x * 128;
    int tid = threadIdx.x;
    int lane = tid & 31, w = tid >> 5;

    size_t abase = ((size_t)l * DDIM + d0) * 32;
    for (int i = tid; i < 128 * 32; i += 512) As[i] = A[abase + i];
    __syncthreads();

    int pbeg = g_start[l], pend = g_start[l + 1];
    for (int p = pbeg + w; p < pend; p += 16) {
        int t = g_tok[p];
        float xv[4];
#pragma unroll
        for (int s = 0; s < 4; ++s)
            xv[s] = x[(size_t)t * DDIM + d0 + s * 32 + lane];
        float acc = 0.0f;
#pragma unroll
        for (int s = 0; s < 4; ++s) {
#pragma unroll
            for (int i = 0; i < 32; ++i) {
                float xb = __shfl_sync(0xffffffffu, xv[s], i);
                acc += xb * As[(s * 32 + i) * 32 + lane];
            }
        }
        atomicAdd(&g_xa[t * 32 + lane], acc);
    }
}

// ------- kernel 4: delta -> out (full init), B in regs, 2-token ILP ----------
__global__ __launch_bounds__(256) void delta_kernel(const float* __restrict__ B,
                                                    float* __restrict__ out) {
    int l = blockIdx.y;
    int n0 = blockIdx.x * 512;
    int half = (n0 >= HALF_B) ? 1 : 0;
    int tid = threadIdx.x;
    int c0 = n0 + 2 * tid;

    int pbeg = g_start[l], pend = g_start[l + 1];
    int len = pend - pbeg;
    int per = (len + 3) >> 2;
    int s = pbeg + blockIdx.z * per;
    int e = s + per;
    if (e > pend) e = pend;
    if (s >= e) return;

    float2 Breg[16];
#pragma unroll
    for (int r = 0; r < 16; ++r)
        Breg[r] = *(const float2*)(B + ((size_t)l * 16 + r) * NOUT + c0);

    const float4* xa4base = (const float4*)(g_xa) + half * 4;

    int p = s;
    for (; p + 1 < e; p += 2) {
        int t0 = g_tok[p];
        int t1 = g_tok[p + 1];
        // both tokens' xa loads issue together (MLP=8 broadcast LDG.128)
        float4 a0 = __ldg(xa4base + t0 * 8 + 0);
        float4 a1 = __ldg(xa4base + t0 * 8 + 1);
        float4 a2 = __ldg(xa4base + t0 * 8 + 2);
        float4 a3 = __ldg(xa4base + t0 * 8 + 3);
        float4 b0 = __ldg(xa4base + t1 * 8 + 0);
        float4 b1 = __ldg(xa4base + t1 * 8 + 1);
        float4 b2 = __ldg(xa4base + t1 * 8 + 2);
        float4 b3 = __ldg(xa4base + t1 * 8 + 3);
        float xs0[16] = {a0.x, a0.y, a0.z, a0.w, a1.x, a1.y, a1.z, a1.w,
                         a2.x, a2.y, a2.z, a2.w, a3.x, a3.y, a3.z, a3.w};
        float xs1[16] = {b0.x, b0.y, b0.z, b0.w, b1.x, b1.y, b1.z, b1.w,
                         b2.x, b2.y, b2.z, b2.w, b3.x, b3.y, b3.z, b3.w};
        float2 acc0 = make_float2(0.0f, 0.0f);
        float2 acc1 = make_float2(0.0f, 0.0f);
#pragma unroll
        for (int r = 0; r < 16; ++r) {
            acc0.x += xs0[r] * Breg[r].x;
            acc0.y += xs0[r] * Breg[r].y;
            acc1.x += xs1[r] * Breg[r].x;
            acc1.y += xs1[r] * Breg[r].y;
        }
        *(float2*)(out + (size_t)t0 * NOUT + c0) = acc0;
        *(float2*)(out + (size_t)t1 * NOUT + c0) = acc1;
    }
    if (p < e) {
        int t = g_tok[p];
        float4 a0 = __ldg(xa4base + t * 8 + 0);
        float4 a1 = __ldg(xa4base + t * 8 + 1);
        float4 a2 = __ldg(xa4base + t * 8 + 2);
        float4 a3 = __ldg(xa4base + t * 8 + 3);
        float xs[16] = {a0.x, a0.y, a0.z, a0.w, a1.x, a1.y, a1.z, a1.w,
                        a2.x, a2.y, a2.z, a2.w, a3.x, a3.y, a3.z, a3.w};
        float2 acc = make_float2(0.0f, 0.0f);
#pragma unroll
        for (int r = 0; r < 16; ++r) {
            acc.x += xs[r] * Breg[r].x;
            acc.y += xs[r] * Breg[r].y;
        }
        *(float2*)(out + (size_t)t * NOUT + c0) = acc;
    }
}

// ------- kernel 5: main GEMM (fp16 mma.sync m16n8k16, BK=64, 2 stages) -------
#define BM 128
#define BN 128
#define BK 64
#define PADH 72                         // halfs per smem row: 144 B stride (16B-aligned, conflict-free)
#define STAGE_BYTES ((BM + BN) * PADH * 2)   // 36864 B
#define SMEM_GEMM (2 * STAGE_BYTES)          // 73728 B -> 2 CTAs/SM, 81 KB L1 left

__device__ __forceinline__ void cpa16(uint32_t s, const void* g) {
    asm volatile("cp.async.cg.shared.global [%0], [%1], 16;\n" :: "r"(s), "l"(g));
}

__global__ __launch_bounds__(256, 2) void gemm_kernel(float* __restrict__ out) {
    extern __shared__ __half smem[];

    int tid = threadIdx.x;
    int lane = tid & 31;
    int warp = tid >> 5;
    int warpM = warp & 3;    // 4 warps in M  -> 32 rows each
    int warpN = warp >> 2;   // 2 warps in N  -> 64 cols each
    int grp = lane >> 2;     // 0..7
    int qid = lane & 3;      // 0..3

    int bm = blockIdx.x;     // 0..15
    int bn = blockIdx.y;     // 0..87

    const __half* gA = g_xh + (size_t)(bm * BM) * DDIM;
    const __half* gB = g_wh + (size_t)(bn * BN) * DDIM;

    // cp.async mapping: 256 rows x 8 segs of 16B (128 B per row); 8 chunks/thread
    int rbase = tid >> 3;    // 0..31
    int seg = tid & 7;       // 0..7

    uint32_t sBase = (uint32_t)__cvta_generic_to_shared(smem);

    float c[2][8][4];
#pragma unroll
    for (int mt = 0; mt < 2; ++mt)
#pragma unroll
        for (int nt = 0; nt < 8; ++nt)
#pragma unroll
            for (int i = 0; i < 4; ++i) c[mt][nt][i] = 0.0f;

    auto loadTiles = [&](int buf, int k0) {
        uint32_t soff = sBase + (uint32_t)buf * STAGE_BYTES;
#pragma unroll
        for (int i = 0; i < 8; ++i) {
            int row = rbase + i * 32;          // 0..255 (A rows 0-127, B rows 128-255)
            const __half* src = (row < BM)
                ? (gA + (size_t)row * DDIM + k0 + seg * 8)
                : (gB + (size_t)(row - BM) * DDIM + k0 + seg * 8);
            cpa16(soff + (uint32_t)(row * PADH * 2 + seg * 16), src);
        }
        asm volatile("cp.async.commit_group;\n");
    };

    auto compute = [&](uint32_t base) {   // base = sBase + buf*STAGE_BYTES
        uint32_t aRowOff = (uint32_t)((warpM * 32 + grp) * PADH * 2);
        uint32_t bRowOff = (uint32_t)(BM * PADH * 2 + (warpN * 64 + grp) * PADH * 2);
#pragma unroll
        for (int ks = 0; ks < 4; ++ks) {     // four k16 steps cover BK=64
            uint32_t kb = (uint32_t)(ks * 32 + qid * 4);   // byte offset in row
            uint32_t a[2][4], b[8][2];
#pragma unroll
            for (int mt = 0; mt < 2; ++mt) {
                uint32_t r0 = base + aRowOff + (uint32_t)(mt * 16 * PADH * 2) + kb;
                uint32_t r1 = r0 + (uint32_t)(8 * PADH * 2);
                asm volatile("ld.shared.b32 %0, [%1];" : "=r"(a[mt][0]) : "r"(r0));
                asm volatile("ld.shared.b32 %0, [%1];" : "=r"(a[mt][1]) : "r"(r1));
                asm volatile("ld.shared.b32 %0, [%1];" : "=r"(a[mt][2]) : "r"(r0 + 16));
                asm volatile("ld.shared.b32 %0, [%1];" : "=r"(a[mt][3]) : "r"(r1 + 16));
            }
#pragma unroll
            for (int nt = 0; nt < 8; ++nt) {
                uint32_t rb = base + bRowOff + (uint32_t)(nt * 8 * PADH * 2) + kb;
                asm volatile("ld.shared.b32 %0, [%1];" : "=r"(b[nt][0]) : "r"(rb));
                asm volatile("ld.shared.b32 %0, [%1];" : "=r"(b[nt][1]) : "r"(rb + 16));
            }
#pragma unroll
            for (int mt = 0; mt < 2; ++mt) {
#pragma unroll
                for (int nt = 0; nt < 8; ++nt) {
                    asm volatile(
                        "mma.sync.aligned.m16n8k16.row.col.f32.f16.f16.f32 "
                        "{%0,%1,%2,%3}, {%4,%5,%6,%7}, {%8,%9}, {%0,%1,%2,%3};\n"
                        : "+f"(c[mt][nt][0]), "+f"(c[mt][nt][1]),
                          "+f"(c[mt][nt][2]), "+f"(c[mt][nt][3])
                        : "r"(a[mt][0]), "r"(a[mt][1]), "r"(a[mt][2]), "r"(a[mt][3]),
                          "r"(b[nt][0]), "r"(b[nt][1]));
                }
            }
        }
    };

    loadTiles(0, 0);

    const int NITER = DDIM / BK;   // 32
    // double buffer, unrolled x2 so stage bases are compile-time constants.
#pragma unroll 1
    for (int it = 0; it < NITER; it += 2) {
        // --- iter it (buf 0) ---
        asm volatile("cp.async.wait_group 0;\n");
        __syncthreads();
        loadTiles(1, (it + 1) * BK);
        compute(sBase);
        // --- iter it+1 (buf 1) ---
        asm volatile("cp.async.wait_group 0;\n");
        __syncthreads();
        if (it + 2 < NITER)
            loadTiles(0, (it + 2) * BK);
        compute(sBase + STAGE_BYTES);
    }

    // epilogue: out += acc (out already holds delta)
#pragma unroll
    for (int mt = 0; mt < 2; ++mt) {
#pragma unroll
        for (int nt = 0; nt < 8; ++nt) {
            int r = bm * BM + warpM * 32 + mt * 16 + grp;
            int col = bn * BN + warpN * 64 + nt * 8 + qid * 2;
            size_t o = (size_t)r * NOUT + col;
            float2* p0 = (float2*)(out + o);
            float2 v0 = *p0;
            v0.x += c[mt][nt][0];
            v0.y += c[mt][nt][1];
            *p0 = v0;
            float2* p1 = (float2*)(out + o + (size_t)8 * NOUT);
            float2 v1 = *p1;
            v1.x += c[mt][nt][2];
            v1.y += c[mt][nt][3];
            *p1 = v1;
        }
    }
}

// ---------------- launch ----------------
extern "C" void kernel_launch(void* const* d_in, const int* in_sizes, int n_in,
                              void* d_out, int out_size) {
    const float* x = (const float*)d_in[0];
    const float* W = (const float*)d_in[1];
    const float* A = (const float*)d_in[2];
    const float* B = (const float*)d_in[3];
    const void*  idx = d_in[4];
    float* out = (float*)d_out;

    (void)in_sizes; (void)n_in; (void)out_size;

    cudaFuncSetAttribute(gemm_kernel, cudaFuncAttributeMaxDynamicSharedMemorySize, SMEM_GEMM);

    sort_kernel<<<1, 1024>>>(idx);
    round_kernel<<<2048, 256>>>((const float4*)x, (const float4*)W);
    xa_kernel<<<dim3(16, 16), 512>>>(x, A);
    delta_kernel<<<dim3(22, 16, 4), 256>>>(B, out);
    gemm_kernel<<<dim3(16, 88), 256, SMEM_GEMM>>>(out);
}